// round 3
// baseline (speedup 1.0000x reference)
#include <cuda_runtime.h>
#include <cuda_bf16.h>
#include <cstdint>

// RWKV WKV recurrence, chunked-scan formulation with decoupled lookback.
//   a_t = exp(w_t)*a_{t-1} + exp(k_t)
//   b_t = exp(w_t)*b_{t-1} + exp(k_t)*v_t
//   out_t = b_t / a_t
// Linear state recurrence => over a chunk: s_end = P * s_start + local,
// P = exp(sum w). Chunks processed by independent blocks (high occupancy);
// inclusive chunk prefixes propagate via global scratch + acquire/release
// flags (decoupled lookback). Chunk data is staged in SMEM via cp.async so
// phase B (output replay) never re-reads DRAM: total traffic = 3 reads + 1
// write = 537 MB (floor ~67us).

#define BATCH 16
#define TLEN  2048
#define DIM   1024
#define TC    32
#define NC    (TLEN / TC)              // 64
#define GPB   (DIM / 128)              // 8 d-groups per batch
#define BLOCKS_PER_CHUNK (BATCH * GPB) // 128

__device__ float g_incA[BATCH * NC * DIM];   // inclusive prefix A per (b, c, d)
__device__ float g_incB[BATCH * NC * DIM];   // inclusive prefix B per (b, c, d)
__device__ int   g_flag[BATCH * NC * GPB];   // ready flag per (b, c, g)

__global__ void init_flags_kernel() {
    int i = blockIdx.x * blockDim.x + threadIdx.x;
    if (i < BATCH * NC * GPB) g_flag[i] = 0;
}

__device__ __forceinline__ void cp_async16(uint32_t s, const void* g) {
    asm volatile("cp.async.cg.shared.global [%0], [%1], 16;" :: "r"(s), "l"(g));
}

__global__ __launch_bounds__(128, 4)
void wkv_chunk_kernel(const float* __restrict__ K,
                      const float* __restrict__ V,
                      const float* __restrict__ W,
                      float* __restrict__ O) {
    __shared__ float sK[TC * 128];   // raw k -> overwritten with exp(k)
    __shared__ float sV[TC * 128];   // raw v (kept raw)
    __shared__ float sW[TC * 128];   // raw w -> overwritten with exp(w)

    const int tid = threadIdx.x;
    const int bid = blockIdx.x;
    const int c   = bid >> 7;        // chunk index (slowest-varying: deps point to lower bids)
    const int bg  = bid & 127;
    const int b   = bg >> 3;
    const int g   = bg & 7;

    const size_t chunkBase = ((size_t)b * TLEN + (size_t)c * TC) * DIM + (size_t)g * 128;

    // ---- async bulk load of the chunk's k, v, w into SMEM (16B tiles) ----
    {
        uint32_t skA = (uint32_t)__cvta_generic_to_shared(sK);
        uint32_t svA = (uint32_t)__cvta_generic_to_shared(sV);
        uint32_t swA = (uint32_t)__cvta_generic_to_shared(sW);
        const char* gK = (const char*)(K + chunkBase);
        const char* gV = (const char*)(V + chunkBase);
        const char* gW = (const char*)(W + chunkBase);
#pragma unroll
        for (int j = 0; j < (TC * 32) / 128; j++) {   // 8 tiles/thread/array
            int tile = tid + 128 * j;
            int t    = tile >> 5;                     // row within chunk
            int col  = tile & 31;                     // 16B column within 512B row
            uint32_t soff = (uint32_t)(t * 512 + col * 16);
            size_t   goff = (size_t)t * (DIM * 4) + (size_t)col * 16;
            cp_async16(skA + soff, gK + goff);
            cp_async16(svA + soff, gV + goff);
            cp_async16(swA + soff, gW + goff);
        }
        asm volatile("cp.async.commit_group;");
        asm volatile("cp.async.wait_group 0;" ::: "memory");
    }
    __syncthreads();

    // ---- Phase A: local scan (zero initial state) + chunk aggregate ----
    float aL = 0.0f, bL = 0.0f, sumw = 0.0f;
#pragma unroll 8
    for (int t = 0; t < TC; t++) {
        float lk = sK[t * 128 + tid];
        float lv = sV[t * 128 + tid];
        float lw = sW[t * 128 + tid];
        float ew = __expf(lw);
        float ek = __expf(lk);
        sumw += lw;
        aL = fmaf(ew, aL, ek);
        bL = fmaf(ew, bL, ek * lv);
        sK[t * 128 + tid] = ek;   // cache transformed values for phase B
        sW[t * 128 + tid] = ew;
    }
    const float P = __expf(sumw);   // prod(ew) over chunk

    // ---- Lookback: wait for predecessor's inclusive prefix, publish ours ----
    float Aprev = 0.0f, Bprev = 0.0f;
    if (c > 0) {
        const int pflag = ((b * NC) + (c - 1)) * GPB + g;
        if (tid == 0) {
            int f = 0;
            do {
                asm volatile("ld.acquire.gpu.global.b32 %0, [%1];"
                             : "=r"(f) : "l"(&g_flag[pflag]) : "memory");
                if (!f) __nanosleep(40);
            } while (f == 0);
        }
        __syncthreads();   // chain t0's acquire to all threads
        const size_t pidx = ((size_t)b * NC + (c - 1)) * DIM + (size_t)g * 128 + tid;
        Aprev = __ldcg(&g_incA[pidx]);
        Bprev = __ldcg(&g_incB[pidx]);
    }
    if (c < NC - 1) {
        const size_t idx = ((size_t)b * NC + c) * DIM + (size_t)g * 128 + tid;
        g_incA[idx] = fmaf(P, Aprev, aL);
        g_incB[idx] = fmaf(P, Bprev, bL);
        __threadfence();
        __syncthreads();
        if (tid == 0) {
            const int flag = ((b * NC) + c) * GPB + g;
            asm volatile("st.release.gpu.global.b32 [%0], %1;"
                         :: "l"(&g_flag[flag]), "r"(1) : "memory");
        }
    }

    // ---- Phase B: replay recurrence from exclusive prefix, write outputs ----
    float a = Aprev, s = Bprev;
    float* out = O + chunkBase + tid;
#pragma unroll 8
    for (int t = 0; t < TC; t++) {
        float ew = sW[t * 128 + tid];
        float ek = sK[t * 128 + tid];
        float lv = sV[t * 128 + tid];
        a = fmaf(ew, a, ek);
        s = fmaf(ew, s, ek * lv);
        out[(size_t)t * DIM] = __fdividef(s, a);
    }
}

extern "C" void kernel_launch(void* const* d_in, const int* in_sizes, int n_in,
                              void* d_out, int out_size) {
    const float* k = (const float*)d_in[0];
    const float* v = (const float*)d_in[1];
    const float* w = (const float*)d_in[2];
    float* out = (float*)d_out;

    init_flags_kernel<<<8, 1024>>>();
    wkv_chunk_kernel<<<NC * BLOCKS_PER_CHUNK, 128>>>(k, v, w, out);
}

// round 4
// speedup vs baseline: 1.1619x; 1.1619x over previous
#include <cuda_runtime.h>
#include <cuda_bf16.h>
#include <cstdint>

// RWKV WKV recurrence, chunked scan with TRUE decoupled lookback (CUB-style).
//   a_t = exp(w_t)*a_{t-1} + exp(k_t)
//   b_t = exp(w_t)*b_{t-1} + exp(k_t)*v_t
//   out_t = b_t / a_t
// Each block = one (batch, chunk, 128-wide d-group). After the local scan it
// publishes its chunk AGGREGATE (P, aL, bL) immediately (flag=1, no waiting),
// then scans backward combining predecessor aggregates until it finds an
// INCLUSIVE prefix (flag=2), publishes its own inclusive, and replays the
// recurrence from the exclusive prefix using smem-cached exp(k)/exp(w)/v.
// Single-pass DRAM traffic (~560MB incl. scratch) -> floor ~72us.

#define BATCH 16
#define TLEN  2048
#define DIM   1024
#define TC    32
#define NC    (TLEN / TC)              // 64
#define GPB   (DIM / 128)              // 8 d-groups per batch
#define BLOCKS_PER_CHUNK (BATCH * GPB) // 128

// Scratch: per (b, c, d) aggregate and inclusive values; per (b, c, g) flag.
__device__ float g_P [BATCH * NC * DIM];   // chunk aggregate: prod(ew)
__device__ float g_aA[BATCH * NC * DIM];   // chunk aggregate: local a
__device__ float g_aB[BATCH * NC * DIM];   // chunk aggregate: local b
__device__ float g_iA[BATCH * NC * DIM];   // inclusive prefix a
__device__ float g_iB[BATCH * NC * DIM];   // inclusive prefix b
__device__ int   g_flag[BATCH * NC * GPB]; // 0=none, 1=aggregate, 2=inclusive

__global__ void init_flags_kernel() {
    int i = blockIdx.x * blockDim.x + threadIdx.x;
    if (i < BATCH * NC * GPB) g_flag[i] = 0;
}

__device__ __forceinline__ void cp_async16(uint32_t s, const void* g) {
    asm volatile("cp.async.cg.shared.global [%0], [%1], 16;" :: "r"(s), "l"(g));
}

__global__ __launch_bounds__(128, 4)
void wkv_lookback_kernel(const float* __restrict__ K,
                         const float* __restrict__ V,
                         const float* __restrict__ W,
                         float* __restrict__ O) {
    __shared__ float sK[TC * 128];   // raw k -> overwritten with exp(k)
    __shared__ float sV[TC * 128];   // raw v
    __shared__ float sW[TC * 128];   // raw w -> overwritten with exp(w)
    __shared__ int   sflag;

    const int tid = threadIdx.x;
    const int bid = blockIdx.x;
    const int c   = bid >> 7;        // chunk index (slowest: predecessors have lower bid)
    const int bg  = bid & 127;
    const int b   = bg >> 3;
    const int g   = bg & 7;

    const size_t chunkBase = ((size_t)b * TLEN + (size_t)c * TC) * DIM + (size_t)g * 128;
    const size_t myIdx = ((size_t)(b * NC + c)) * DIM + (size_t)g * 128 + tid;
    const int    myFlag = (b * NC + c) * GPB + g;

    // ---- async bulk load of chunk k, v, w into SMEM ----
    {
        uint32_t skA = (uint32_t)__cvta_generic_to_shared(sK);
        uint32_t svA = (uint32_t)__cvta_generic_to_shared(sV);
        uint32_t swA = (uint32_t)__cvta_generic_to_shared(sW);
        const char* gK = (const char*)(K + chunkBase);
        const char* gV = (const char*)(V + chunkBase);
        const char* gW = (const char*)(W + chunkBase);
#pragma unroll
        for (int j = 0; j < (TC * 32) / 128; j++) {   // 8 16B tiles/thread/array
            int tile = tid + 128 * j;
            int t    = tile >> 5;
            int col  = tile & 31;
            uint32_t soff = (uint32_t)(t * 512 + col * 16);
            size_t   goff = (size_t)t * (DIM * 4) + (size_t)col * 16;
            cp_async16(skA + soff, gK + goff);
            cp_async16(svA + soff, gV + goff);
            cp_async16(swA + soff, gW + goff);
        }
        asm volatile("cp.async.commit_group;");
        asm volatile("cp.async.wait_group 0;" ::: "memory");
    }
    __syncthreads();

    // ---- Phase A: local scan from zero state + chunk aggregate ----
    float aL = 0.0f, bL = 0.0f, sumw = 0.0f;
#pragma unroll 8
    for (int t = 0; t < TC; t++) {
        float lk = sK[t * 128 + tid];
        float lv = sV[t * 128 + tid];
        float lw = sW[t * 128 + tid];
        float ew = __expf(lw);
        float ek = __expf(lk);
        sumw += lw;
        aL = fmaf(ew, aL, ek);
        bL = fmaf(ew, bL, ek * lv);
        sK[t * 128 + tid] = ek;   // cache for phase B
        sW[t * 128 + tid] = ew;
    }
    const float P = __expf(sumw);

    // ---- Publish: c==0 publishes INCLUSIVE directly; others publish AGGREGATE now ----
    if (c == 0) {
        g_iA[myIdx] = aL;
        g_iB[myIdx] = bL;
        __syncthreads();
        if (tid == 0) {
            __threadfence();
            asm volatile("st.release.gpu.global.b32 [%0], %1;"
                         :: "l"(&g_flag[myFlag]), "r"(2) : "memory");
        }
    } else {
        g_P [myIdx] = P;
        g_aA[myIdx] = aL;
        g_aB[myIdx] = bL;
        __syncthreads();
        if (tid == 0) {
            __threadfence();
            asm volatile("st.release.gpu.global.b32 [%0], %1;"
                         :: "l"(&g_flag[myFlag]), "r"(1) : "memory");
        }
    }

    // ---- Decoupled lookback: combine predecessor aggregates backward ----
    float accA = 0.0f, accB = 0.0f, accP = 1.0f;   // exclusive prefix for chunk c
    if (c > 0) {
        int j = c - 1;
        while (true) {
            if (tid == 0) {
                int f;
                const int* fp = &g_flag[(b * NC + j) * GPB + g];
                do {
                    asm volatile("ld.acquire.gpu.global.b32 %0, [%1];"
                                 : "=r"(f) : "l"(fp) : "memory");
                    if (!f) __nanosleep(20);
                } while (f == 0);
                sflag = f;
            }
            __syncthreads();
            const int f = sflag;
            __syncthreads();   // sflag safe for reuse next iteration
            const size_t jIdx = ((size_t)(b * NC + j)) * DIM + (size_t)g * 128 + tid;
            if (f == 2) {
                accA = fmaf(accP, __ldcg(&g_iA[jIdx]), accA);
                accB = fmaf(accP, __ldcg(&g_iB[jIdx]), accB);
                break;
            } else {
                accA = fmaf(accP, __ldcg(&g_aA[jIdx]), accA);
                accB = fmaf(accP, __ldcg(&g_aB[jIdx]), accB);
                accP *= __ldcg(&g_P[jIdx]);
                j--;
            }
        }

        // Publish own inclusive prefix (skip for last chunk: no successors)
        if (c < NC - 1) {
            g_iA[myIdx] = fmaf(P, accA, aL);
            g_iB[myIdx] = fmaf(P, accB, bL);
            __syncthreads();
            if (tid == 0) {
                __threadfence();
                asm volatile("st.release.gpu.global.b32 [%0], %1;"
                             :: "l"(&g_flag[myFlag]), "r"(2) : "memory");
            }
        }
    }

    // ---- Phase B: replay recurrence from exclusive prefix, write outputs ----
    float a = accA, s = accB;
    float* out = O + chunkBase + tid;
#pragma unroll 8
    for (int t = 0; t < TC; t++) {
        float ew = sW[t * 128 + tid];
        float ek = sK[t * 128 + tid];
        float lv = sV[t * 128 + tid];
        a = fmaf(ew, a, ek);
        s = fmaf(ew, s, ek * lv);
        out[(size_t)t * DIM] = __fdividef(s, a);
    }
}

extern "C" void kernel_launch(void* const* d_in, const int* in_sizes, int n_in,
                              void* d_out, int out_size) {
    const float* k = (const float*)d_in[0];
    const float* v = (const float*)d_in[1];
    const float* w = (const float*)d_in[2];
    float* out = (float*)d_out;

    init_flags_kernel<<<8, 1024>>>();
    wkv_lookback_kernel<<<NC * BLOCKS_PER_CHUNK, 128>>>(k, v, w, out);
}

// round 5
// speedup vs baseline: 1.9428x; 1.6720x over previous
#include <cuda_runtime.h>
#include <cuda_bf16.h>
#include <cstdint>

// RWKV WKV recurrence, single-pass serial-in-T with a deep cp.async smem ring.
//   a_t = exp(w_t)*a_{t-1} + exp(k_t)
//   b_t = exp(w_t)*b_{t-1} + exp(k_t)*v_t
//   out_t = b_t / a_t
// One block per (batch, 64-wide d-group): 256 blocks x 64 threads. Each block
// walks T=2048 serially; k/v/w are prefetched ~56 steps ahead into a 48KB
// smem ring via cp.async (8 batches x 8 steps), so DRAM demand is decoupled
// from the serial recurrence. No inter-block sync, no scratch traffic:
// 537MB total -> ~67us floor at 8TB/s.

#define BATCH 16
#define TLEN  2048
#define DIM   1024
#define GROUP 64
#define SPB   8                        // steps per batch
#define NB    8                        // ring depth in batches (64 steps)
#define NBT   (TLEN / SPB)             // 256 total batches
#define TILES_PER_BATCH (3 * SPB * (GROUP * 4 / 16))   // 3 arrays * 8 steps * 16 tiles = 384
#define TILES_PER_THREAD (TILES_PER_BATCH / GROUP)     // 6

__device__ __forceinline__ void cp_async16(uint32_t s, const void* g) {
    asm volatile("cp.async.cg.shared.global [%0], [%1], 16;" :: "r"(s), "l"(g));
}

__global__ __launch_bounds__(GROUP)
void wkv_ring_kernel(const float* __restrict__ K,
                     const float* __restrict__ V,
                     const float* __restrict__ W,
                     float* __restrict__ O) {
    // ring[slot][arr][step][d] : slot<8, arr<3, step<8, d<64
    __shared__ float ring[NB * 3 * SPB * GROUP];   // 48 KB

    const int tid = threadIdx.x;
    const int b   = blockIdx.x >> 4;          // batch
    const int g   = blockIdx.x & 15;          // d-group

    const size_t rowBase = (size_t)b * TLEN * DIM + (size_t)g * GROUP;  // element offset of (b, t=0, group)
    const uint32_t sBase = (uint32_t)__cvta_generic_to_shared(ring);

    const float* arrs[3] = { K, V, W };

    // Issue all cp.asyncs for one batch (8 steps x 3 arrays x 256B rows).
    auto issue_batch = [&](int bt) {
        const int slot = bt & (NB - 1);
        const int step0 = bt * SPB;
#pragma unroll
        for (int j = 0; j < TILES_PER_THREAD; j++) {
            int i   = tid + GROUP * j;        // 0..383
            int arr = i >> 7;                 // /128  (16 tiles * 8 steps per array)
            int rem = i & 127;
            int t   = rem >> 4;               // step within batch
            int col = rem & 15;               // 16B column within 256B row
            size_t goff = rowBase + (size_t)(step0 + t) * DIM + (size_t)col * 4;
            uint32_t soff = (uint32_t)((((slot * 3 + arr) * SPB + t) * GROUP + col * 4) * 4);
            cp_async16(sBase + soff, arrs[arr] + goff);
        }
    };

    // ---- prologue: fill NB-1 ring slots ----
#pragma unroll
    for (int bt = 0; bt < NB - 1; bt++) {
        issue_batch(bt);
        asm volatile("cp.async.commit_group;");
    }

    float a = 0.0f, s = 0.0f;
    float* out = O + rowBase + tid;

    for (int bt = 0; bt < NBT; bt++) {
        // Keep the pipeline full; commit every iteration (possibly empty group)
        // so the wait_group arithmetic stays uniform through the tail.
        if (bt + NB - 1 < NBT) issue_batch(bt + NB - 1);
        asm volatile("cp.async.commit_group;");
        asm volatile("cp.async.wait_group %0;" :: "n"(NB - 2) : "memory");
        __syncthreads();   // make this slot's data visible to all threads

        const int slot = bt & (NB - 1);
        const float* rk = &ring[((slot * 3 + 0) * SPB) * GROUP + tid];
        const float* rv = &ring[((slot * 3 + 1) * SPB) * GROUP + tid];
        const float* rw = &ring[((slot * 3 + 2) * SPB) * GROUP + tid];

#pragma unroll
        for (int u = 0; u < SPB; u++) {
            float lk = rk[u * GROUP];
            float lv = rv[u * GROUP];
            float lw = rw[u * GROUP];
            float ek = __expf(lk);
            float ew = __expf(lw);
            a = fmaf(ew, a, ek);
            s = fmaf(ew, s, ek * lv);
            out[(size_t)(bt * SPB + u) * DIM] = __fdividef(s, a);
        }
        __syncthreads();   // all reads done before this slot is overwritten
    }
}

extern "C" void kernel_launch(void* const* d_in, const int* in_sizes, int n_in,
                              void* d_out, int out_size) {
    const float* k = (const float*)d_in[0];
    const float* v = (const float*)d_in[1];
    const float* w = (const float*)d_in[2];
    float* out = (float*)d_out;

    wkv_ring_kernel<<<BATCH * (DIM / GROUP), GROUP>>>(k, v, w, out);
}

// round 6
// speedup vs baseline: 1.9639x; 1.0109x over previous
#include <cuda_runtime.h>
#include <cuda_bf16.h>
#include <cstdint>

// RWKV WKV recurrence, single-pass serial-in-T, warp-per-block cp.async ring.
//   a_t = exp(w_t)*a_{t-1} + exp(k_t)
//   b_t = exp(w_t)*b_{t-1} + exp(k_t)*v_t
//   out_t = b_t / a_t
// One 32-thread block per (batch, 32-wide d-group): 512 blocks. Each block
// walks T=2048 serially; k/v/w are prefetched ~56 steps ahead into a 24KB
// smem ring (8 slots x 8 steps) via cp.async. Warp-scope sync only
// (__syncwarp), so there are no cross-warp barrier bubbles in the 256-iter
// steady state. Output uses streaming stores to avoid L2 pollution.
// Minimal traffic: 3 reads + 1 write = 537MB.

#define BATCH 16
#define TLEN  2048
#define DIM   1024
#define GROUP 32
#define SPB   8                        // steps per ring slot
#define NB    8                        // ring depth in slots (64 steps lead)
#define NBT   (TLEN / SPB)             // 256 iterations
#define TILES_PER_BATCH (3 * SPB * (GROUP * 4 / 16))   // 3 * 8 * 8 = 192
#define TILES_PER_THREAD (TILES_PER_BATCH / GROUP)     // 6

__device__ __forceinline__ void cp_async16(uint32_t s, const void* g) {
    asm volatile("cp.async.cg.shared.global [%0], [%1], 16;" :: "r"(s), "l"(g));
}

__global__ __launch_bounds__(GROUP, 4)
void wkv_warp_ring_kernel(const float* __restrict__ K,
                          const float* __restrict__ V,
                          const float* __restrict__ W,
                          float* __restrict__ O) {
    // ring[slot][arr][step][d] : slot<8, arr<3, step<8, d<32
    __shared__ float ring[NB * 3 * SPB * GROUP];   // 24 KB

    const int tid = threadIdx.x;
    const int b   = blockIdx.x >> 5;          // batch
    const int g   = blockIdx.x & 31;          // d-group of 32

    const size_t rowBase = (size_t)b * TLEN * DIM + (size_t)g * GROUP;
    const uint32_t sBase = (uint32_t)__cvta_generic_to_shared(ring);

    const float* arrs[3] = { K, V, W };

    // Issue all cp.asyncs for one ring slot (8 steps x 3 arrays x 128B rows).
    auto issue_batch = [&](int bt) {
        const int slot = bt & (NB - 1);
        const int step0 = bt * SPB;
#pragma unroll
        for (int j = 0; j < TILES_PER_THREAD; j++) {
            int i   = tid + GROUP * j;        // 0..191
            int arr = i >> 6;                 // /64  (8 tiles * 8 steps per array)
            int rem = i & 63;
            int t   = rem >> 3;               // step within slot
            int col = rem & 7;                // 16B column within 128B row
            size_t goff = rowBase + (size_t)(step0 + t) * DIM + (size_t)col * 4;
            uint32_t soff = (uint32_t)((((slot * 3 + arr) * SPB + t) * GROUP + col * 4) * 4);
            cp_async16(sBase + soff, arrs[arr] + goff);
        }
    };

    // ---- prologue: fill NB-1 ring slots ----
#pragma unroll
    for (int bt = 0; bt < NB - 1; bt++) {
        issue_batch(bt);
        asm volatile("cp.async.commit_group;");
    }

    float a = 0.0f, s = 0.0f;
    float* out = O + rowBase + tid;

    for (int bt = 0; bt < NBT; bt++) {
        // Keep pipeline full; commit every iteration (possibly empty group)
        // so wait_group arithmetic stays uniform through the tail.
        if (bt + NB - 1 < NBT) issue_batch(bt + NB - 1);
        asm volatile("cp.async.commit_group;");
        asm volatile("cp.async.wait_group %0;" :: "n"(NB - 2) : "memory");
        __syncwarp();   // this slot's data visible to all lanes

        const int slot = bt & (NB - 1);
        const float* rk = &ring[((slot * 3 + 0) * SPB) * GROUP + tid];
        const float* rv = &ring[((slot * 3 + 1) * SPB) * GROUP + tid];
        const float* rw = &ring[((slot * 3 + 2) * SPB) * GROUP + tid];

#pragma unroll
        for (int u = 0; u < SPB; u++) {
            float lk = rk[u * GROUP];
            float lv = rv[u * GROUP];
            float lw = rw[u * GROUP];
            float ek = __expf(lk);
            float ew = __expf(lw);
            a = fmaf(ew, a, ek);
            s = fmaf(ew, s, ek * lv);
            __stcs(&out[(size_t)(bt * SPB + u) * DIM], __fdividef(s, a));
        }
        __syncwarp();   // all lanes done reading before slot is overwritten
    }
}

extern "C" void kernel_launch(void* const* d_in, const int* in_sizes, int n_in,
                              void* d_out, int out_size) {
    const float* k = (const float*)d_in[0];
    const float* v = (const float*)d_in[1];
    const float* w = (const float*)d_in[2];
    float* out = (float*)d_out;

    wkv_warp_ring_kernel<<<BATCH * (DIM / GROUP), GROUP>>>(k, v, w, out);
}